// round 11
// baseline (speedup 1.0000x reference)
#include <cuda_runtime.h>
#include <cuda_bf16.h>
#include <cstdint>

// ===========================================================================
// Cross-attention. All GEMMs: bf16 split-precision x3 HMMA (fp32 acc).
// 128x128 block tile, 4 warps (warp 64x64), cp.async 3-stage pipeline,
// __launch_bounds__(128,2) -> 2 CTAs/SM, ~220 regs, 96KB smem/CTA.
// Warp tile 64x64 halves LDSM-per-HMMA vs 64x32 (LSU was co-saturated).
// QKV fused per stage; build_temp fused into PV1 epilogue; V stored VT.
// ===========================================================================

// ---------------- helpers ----------------
__device__ __forceinline__ uint32_t smem_u32(const void* p) {
    uint32_t a;
    asm("{ .reg .u64 t; cvta.to.shared.u64 t, %1; cvt.u32.u64 %0, t; }"
        : "=r"(a) : "l"(p));
    return a;
}
__device__ __forceinline__ void ldsm_x4(uint32_t* r, uint32_t addr) {
    asm volatile("ldmatrix.sync.aligned.m8n8.x4.shared.b16 {%0,%1,%2,%3}, [%4];"
                 : "=r"(r[0]), "=r"(r[1]), "=r"(r[2]), "=r"(r[3]) : "r"(addr));
}
__device__ __forceinline__ void mma16816(float* d, const uint32_t* a,
                                         uint32_t b0, uint32_t b1) {
    asm volatile(
        "mma.sync.aligned.m16n8k16.row.col.f32.bf16.bf16.f32 "
        "{%0,%1,%2,%3}, {%4,%5,%6,%7}, {%8,%9}, {%0,%1,%2,%3};"
        : "+f"(d[0]), "+f"(d[1]), "+f"(d[2]), "+f"(d[3])
        : "r"(a[0]), "r"(a[1]), "r"(a[2]), "r"(a[3]), "r"(b0), "r"(b1));
}
__device__ __forceinline__ void cp16(uint32_t s, const void* g) {
    asm volatile("cp.async.cg.shared.global [%0], [%1], 16;" :: "r"(s), "l"(g));
}
__device__ __forceinline__ void split2(float v0, float v1,
                                       __nv_bfloat162& hh, __nv_bfloat162& ll) {
    __nv_bfloat16 h0 = __float2bfloat16(v0);
    __nv_bfloat16 h1 = __float2bfloat16(v1);
    hh.x = h0; hh.y = h1;
    ll.x = __float2bfloat16(v0 - __bfloat162float(h0));
    ll.y = __float2bfloat16(v1 - __bfloat162float(h1));
}

// ---------------- scratch (static device memory; bf16 hi/lo planes) -------
__device__ __nv_bfloat16 g_xyh[16384LL * 512], g_xyl[16384LL * 512];
__device__ __nv_bfloat16 g_w1h[1536 * 512],   g_w1l[1536 * 512];    // [q;k;v]
__device__ __nv_bfloat16 g_w2h[3072 * 1024],  g_w2l[3072 * 1024];   // [q;k;v]
__device__ float         g_b1[1536], g_b2[3072];
__device__ __nv_bfloat16 g_Q1h[16384LL * 512], g_Q1l[16384LL * 512];
__device__ __nv_bfloat16 g_K1h[16384LL * 512], g_K1l[16384LL * 512];
__device__ __nv_bfloat16 g_VT1h[16384LL * 512], g_VT1l[16384LL * 512]; // [8][512][2048]
__device__ float         g_S [8LL * 2048 * 2048];
__device__ __nv_bfloat16 g_Ph[8LL * 2048 * 2048], g_Pl[8LL * 2048 * 2048];
__device__ __nv_bfloat16 g_Th[8192LL * 1024], g_Tl[8192LL * 1024];
__device__ __nv_bfloat16 g_Q2h[8192LL * 1024], g_Q2l[8192LL * 1024];
__device__ __nv_bfloat16 g_K2h[8192LL * 1024], g_K2l[8192LL * 1024];
__device__ __nv_bfloat16 g_VT2h[8192LL * 1024], g_VT2l[8192LL * 1024]; // [4][1024][2048]

// Stage (32KB): Ah +0 (8K), Al +8192, Bh +16384 (8K), Bl +24576. 3 stages.
static constexpr int STG = 32768;
static constexpr int SMEM_BYTES = 3 * STG;   // 98304 -> 2 CTAs/SM (192KB)

// ===========================================================================
// NT GEMM: C[M,N] = (Ah+Al)[M,K]*(Bh+Bl)[N,K]^T, 3-pass bf16 HMMA, fp32 acc.
// Block tile 128x128, warp tile 64x64 (warps 2m x 2n). Template K.
// MODE: 0 fp32 out; 3 QKV routing; 4 PV1+build_temp.
// ===========================================================================
template<int K, int MODE>
__global__ void __launch_bounds__(128, 2)
gemm_bf3(const __nv_bfloat16* __restrict__ Ah, const __nv_bfloat16* __restrict__ Al,
         const __nv_bfloat16* __restrict__ Bh, const __nv_bfloat16* __restrict__ Bl,
         const float* __restrict__ bias,
         float* __restrict__ Cf,
         __nv_bfloat16* __restrict__ P0h, __nv_bfloat16* __restrict__ P0l,
         __nv_bfloat16* __restrict__ P1h, __nv_bfloat16* __restrict__ P1l,
         __nv_bfloat16* __restrict__ P2h, __nv_bfloat16* __restrict__ P2l,
         const float* __restrict__ rx, const float* __restrict__ ry,
         const float* __restrict__ rw1, const float* __restrict__ rw2,
         int M, int N,
         long long sA, long long sB, long long sC,
         int segN)
{
    extern __shared__ char smem[];
    const uint32_t sb = smem_u32(smem);
    const int tid = threadIdx.x;
    const int lane = tid & 31;
    const int wid = tid >> 5;            // 0..3
    const int z = blockIdx.z;

    const int m0 = blockIdx.y * 128;
    const int n0 = blockIdx.x * 128;
    const int m0w = (wid & 1) * 64;
    const int n0w = (wid >> 1) * 64;

    // cp.async: 128 threads, 16 x 16B each per chunk (A/B both 128 rows)
    const int r0 = tid >> 2, c0 = tid & 3;             // 32 rows x 4 col-groups
    const uint32_t soff0 = (uint32_t)r0 * 64 + (uint32_t)((c0 ^ ((r0 >> 1) & 3)) << 4);
    const __nv_bfloat16* pAh = Ah + (long long)z * sA + (long long)(m0 + r0) * K + c0 * 8;
    const __nv_bfloat16* pAl = Al + (long long)z * sA + (long long)(m0 + r0) * K + c0 * 8;
    const __nv_bfloat16* pBh = Bh + (long long)z * sB + (long long)(n0 + r0) * K + c0 * 8;
    const __nv_bfloat16* pBl = Bl + (long long)z * sB + (long long)(n0 + r0) * K + c0 * 8;
    if (Cf) Cf += (long long)z * sC;

    constexpr int RS = 32 * K;           // 32-row stride (elements), compile-time

    uint32_t iaddr = sb + soff0;                    // rotating cp.async dst
    const uint32_t ilim = sb + soff0 + 3 * STG;

#define ISSUE() do {                                                            \
    cp16(iaddr + 0,     pAh);                                                   \
    cp16(iaddr + 2048,  pAh + RS);                                              \
    cp16(iaddr + 4096,  pAh + 2 * RS);                                          \
    cp16(iaddr + 6144,  pAh + 3 * RS);                                          \
    cp16(iaddr + 8192,  pAl);                                                   \
    cp16(iaddr + 10240, pAl + RS);                                              \
    cp16(iaddr + 12288, pAl + 2 * RS);                                          \
    cp16(iaddr + 14336, pAl + 3 * RS);                                          \
    cp16(iaddr + 16384, pBh);                                                   \
    cp16(iaddr + 18432, pBh + RS);                                              \
    cp16(iaddr + 20480, pBh + 2 * RS);                                          \
    cp16(iaddr + 22528, pBh + 3 * RS);                                          \
    cp16(iaddr + 24576, pBl);                                                   \
    cp16(iaddr + 26624, pBl + RS);                                              \
    cp16(iaddr + 28672, pBl + 2 * RS);                                          \
    cp16(iaddr + 30720, pBl + 3 * RS);                                          \
    asm volatile("cp.async.commit_group;" ::: "memory");                        \
    pAh += 32; pAl += 32; pBh += 32; pBl += 32;                                 \
    iaddr += STG; if (iaddr == ilim) iaddr -= 3 * STG;                          \
} while (0)

    float acc[4][8][4];
#pragma unroll
    for (int i = 0; i < 4; i++)
#pragma unroll
        for (int j = 0; j < 8; j++)
#pragma unroll
            for (int k = 0; k < 4; k++) acc[i][j][k] = 0.f;

    // LDSM base addresses (stage 0, kstep 0); mf/q/plane deltas are immediates
    const int kc0 = lane >> 4;
    const int arow0 = m0w + (lane & 15);
    const int brow0 = n0w + (lane & 15);
    uint32_t a0 = sb + (uint32_t)arow0 * 64
                + (uint32_t)((kc0 ^ ((arow0 >> 1) & 3)) << 4);
    uint32_t b0 = sb + 16384 + (uint32_t)brow0 * 64
                + (uint32_t)((kc0 ^ ((brow0 >> 1) & 3)) << 4);
    const uint32_t alim = a0 + 3 * STG;

    constexpr int nch = K >> 5;
    ISSUE(); ISSUE();

#pragma unroll 1
    for (int ch = 0; ch < nch; ch++) {
        asm volatile("cp.async.wait_group 1;" ::: "memory");
        __syncthreads();
        if (ch + 2 < nch) ISSUE();

#pragma unroll
        for (int kstep = 0; kstep < 2; kstep++) {
            const uint32_t ax = a0 ^ ((uint32_t)kstep << 5);
            const uint32_t bx = b0 ^ ((uint32_t)kstep << 5);
            uint32_t aH[4][4], aL[4][4], bh[4][4], bl[4][4];
            // A-hi + B-hi; pass hh
#pragma unroll
            for (int mf = 0; mf < 4; mf++)
                ldsm_x4(aH[mf], ax + mf * 1024);
#pragma unroll
            for (int q = 0; q < 4; q++)
                ldsm_x4(bh[q], bx + q * 1024);
#pragma unroll
            for (int mf = 0; mf < 4; mf++)
#pragma unroll
                for (int q = 0; q < 4; q++) {
                    mma16816(acc[mf][q * 2 + 0], aH[mf], bh[q][0], bh[q][2]);
                    mma16816(acc[mf][q * 2 + 1], aH[mf], bh[q][1], bh[q][3]);
                }
            // B-lo; pass hl
#pragma unroll
            for (int q = 0; q < 4; q++)
                ldsm_x4(bl[q], bx + 8192 + q * 1024);
#pragma unroll
            for (int mf = 0; mf < 4; mf++)
#pragma unroll
                for (int q = 0; q < 4; q++) {
                    mma16816(acc[mf][q * 2 + 0], aH[mf], bl[q][0], bl[q][2]);
                    mma16816(acc[mf][q * 2 + 1], aH[mf], bl[q][1], bl[q][3]);
                }
            // A-lo; pass lh
#pragma unroll
            for (int mf = 0; mf < 4; mf++)
                ldsm_x4(aL[mf], ax + 8192 + mf * 1024);
#pragma unroll
            for (int mf = 0; mf < 4; mf++)
#pragma unroll
                for (int q = 0; q < 4; q++) {
                    mma16816(acc[mf][q * 2 + 0], aL[mf], bh[q][0], bh[q][2]);
                    mma16816(acc[mf][q * 2 + 1], aL[mf], bh[q][1], bh[q][3]);
                }
        }
        a0 += STG; b0 += STG;
        if (a0 == alim) { a0 -= 3 * STG; b0 -= 3 * STG; }
    }
#undef ISSUE

    // ---- epilogue ----
    const int gr = lane >> 2;
    const int gc = (lane & 3) * 2;

    if (MODE == 0) {
#pragma unroll
        for (int mf = 0; mf < 4; mf++)
#pragma unroll
            for (int nf = 0; nf < 8; nf++) {
                const int row = m0 + m0w + mf * 16 + gr;
                const int col = n0 + n0w + nf * 8 + gc;
                float b0f = 0.f, b1f = 0.f;
                if (bias) { b0f = bias[col]; b1f = bias[col + 1]; }
                float2 v0 = make_float2(acc[mf][nf][0] + b0f, acc[mf][nf][1] + b1f);
                float2 v1 = make_float2(acc[mf][nf][2] + b0f, acc[mf][nf][3] + b1f);
                *reinterpret_cast<float2*>(Cf + (long long)row * N + col) = v0;
                *reinterpret_cast<float2*>(Cf + (long long)(row + 8) * N + col) = v1;
            }
    } else if (MODE == 3) {
        const int seg = n0 / segN;              // CTA-uniform (128 | segN)
        const int cwbase = n0 - seg * segN + n0w;
        if (seg < 2) {
            __nv_bfloat16* Dh = seg ? P1h : P0h;
            __nv_bfloat16* Dl = seg ? P1l : P0l;
#pragma unroll
            for (int mf = 0; mf < 4; mf++)
#pragma unroll
                for (int nf = 0; nf < 8; nf++) {
                    const int row = m0 + m0w + mf * 16 + gr;
                    const int col = cwbase + nf * 8 + gc;
                    const float b0f = bias[n0 + n0w + nf * 8 + gc];
                    const float b1f = bias[n0 + n0w + nf * 8 + gc + 1];
#pragma unroll
                    for (int half = 0; half < 2; half++) {
                        __nv_bfloat162 hh, ll;
                        split2(acc[mf][nf][half * 2 + 0] + b0f,
                               acc[mf][nf][half * 2 + 1] + b1f, hh, ll);
                        const long long idx = (long long)(row + half * 8) * segN + col;
                        *reinterpret_cast<__nv_bfloat162*>(Dh + idx) = hh;
                        *reinterpret_cast<__nv_bfloat162*>(Dl + idx) = ll;
                    }
                }
        } else {
            // V: transposed VT layout, staged via smem (reuses pipeline smem)
            __syncthreads();
            float* tw = reinterpret_cast<float*>(smem) + wid * 4160;  // 64x65
#pragma unroll
            for (int mf = 0; mf < 4; mf++)
#pragma unroll
                for (int nf = 0; nf < 8; nf++) {
                    const int rl = mf * 16 + gr;
                    const int cl = nf * 8 + gc;
                    tw[cl * 65 + rl]           = acc[mf][nf][0];
                    tw[(cl + 1) * 65 + rl]     = acc[mf][nf][1];
                    tw[cl * 65 + rl + 8]       = acc[mf][nf][2];
                    tw[(cl + 1) * 65 + rl + 8] = acc[mf][nf][3];
                }
            __syncwarp();
            const int g0 = m0 + m0w;
            const long long basev =
                (long long)(g0 >> 11) * segN * 2048 + (g0 & 2047);
#pragma unroll 4
            for (int c = 0; c < 64; c++) {
                const int colg = cwbase + c;
                const float bb = bias[n0 + n0w + c];
                const float v0 = tw[c * 65 + lane * 2] + bb;
                const float v1 = tw[c * 65 + lane * 2 + 1] + bb;
                __nv_bfloat162 hh, ll;
                split2(v0, v1, hh, ll);
                const long long idx = basev + (long long)colg * 2048 + lane * 2;
                *reinterpret_cast<__nv_bfloat162*>(P2h + idx) = hh;
                *reinterpret_cast<__nv_bfloat162*>(P2l + idx) = ll;
            }
        }
    } else {
        // MODE 4: PV1 + build_temp fused -> T planes (N=512)
        const float w1v = rw1[0], w2v = rw2[0];
#pragma unroll
        for (int mf = 0; mf < 4; mf++)
#pragma unroll
            for (int nf = 0; nf < 8; nf++) {
                const int col = n0 + n0w + nf * 8 + gc;
#pragma unroll
                for (int half = 0; half < 2; half++) {
                    const int row = m0 + m0w + mf * 16 + gr + half * 8;
                    const int grow = z * 2048 + row;
                    long long tok; int tcol; float2 res;
                    if (grow < 8192) {
                        tok = grow; tcol = col;
                        float2 yy = *reinterpret_cast<const float2*>(
                            ry + tok * 512 + col);
                        res.x = yy.x * w2v; res.y = yy.y * w2v;
                    } else {
                        tok = grow - 8192; tcol = col + 512;
                        float2 xx = *reinterpret_cast<const float2*>(
                            rx + tok * 512 + col);
                        res.x = xx.x * w1v; res.y = xx.y * w1v;
                    }
                    __nv_bfloat162 hh, ll;
                    split2(acc[mf][nf][half * 2 + 0] + res.x,
                           acc[mf][nf][half * 2 + 1] + res.y, hh, ll);
                    const long long idx = tok * 1024 + tcol;
                    *reinterpret_cast<__nv_bfloat162*>(P0h + idx) = hh;
                    *reinterpret_cast<__nv_bfloat162*>(P0l + idx) = ll;
                }
            }
    }
}

// ---------------------------------------------------------------------------
// split x and y fp32 -> stacked bf16 hi/lo planes (float4 granularity)
// ---------------------------------------------------------------------------
__global__ void __launch_bounds__(256)
split_xy(const float* __restrict__ x, const float* __restrict__ y,
         __nv_bfloat16* __restrict__ h, __nv_bfloat16* __restrict__ l,
         long long n4half)
{
    long long i = (long long)blockIdx.x * 256 + threadIdx.x;
    if (i >= 2 * n4half) return;
    const float* s = (i < n4half) ? x : y;
    const long long off = (i < n4half) ? i : i - n4half;
    float4 v = reinterpret_cast<const float4*>(s)[off];
    __nv_bfloat162 h0, l0, h1, l1;
    split2(v.x, v.y, h0, l0);
    split2(v.z, v.w, h1, l1);
    uint2 hh, ll;
    hh.x = *reinterpret_cast<uint32_t*>(&h0); hh.y = *reinterpret_cast<uint32_t*>(&h1);
    ll.x = *reinterpret_cast<uint32_t*>(&l0); ll.y = *reinterpret_cast<uint32_t*>(&l1);
    reinterpret_cast<uint2*>(h)[i] = hh;
    reinterpret_cast<uint2*>(l)[i] = ll;
}

// ---------------------------------------------------------------------------
// split 3 weight matrices into concatenated plane pair + concat biases
// ---------------------------------------------------------------------------
__global__ void __launch_bounds__(256)
split_w3(const float* __restrict__ s0, const float* __restrict__ s1,
         const float* __restrict__ s2,
         const float* __restrict__ b0, const float* __restrict__ b1,
         const float* __restrict__ b2,
         __nv_bfloat16* __restrict__ h, __nv_bfloat16* __restrict__ l,
         float* __restrict__ bcat, int rows, int K)
{
    const long long seglen = (long long)rows * K / 4;   // float4 per segment
    long long i = (long long)blockIdx.x * 256 + threadIdx.x;
    if (i < 3 * seglen) {
        const int seg = (int)(i / seglen);
        const long long off = i - (long long)seg * seglen;
        const float* s = (seg == 0) ? s0 : (seg == 1) ? s1 : s2;
        float4 v = reinterpret_cast<const float4*>(s)[off];
        __nv_bfloat162 h0, l0, h1, l1;
        split2(v.x, v.y, h0, l0);
        split2(v.z, v.w, h1, l1);
        uint2 hh, ll;
        hh.x = *reinterpret_cast<uint32_t*>(&h0); hh.y = *reinterpret_cast<uint32_t*>(&h1);
        ll.x = *reinterpret_cast<uint32_t*>(&l0); ll.y = *reinterpret_cast<uint32_t*>(&l1);
        reinterpret_cast<uint2*>(h)[i] = hh;
        reinterpret_cast<uint2*>(l)[i] = ll;
    }
    const long long t = (long long)blockIdx.x * 256 + threadIdx.x;
    if (t < 3 * rows) {
        const int seg = (int)(t / rows);
        const int off = (int)(t - seg * rows);
        bcat[t] = (seg == 0) ? b0[off] : (seg == 1) ? b1[off] : b2[off];
    }
}

// ---------------------------------------------------------------------------
// Row softmax over 2048 cols; fp32 in, split bf16 hi/lo out. Block = row.
// ---------------------------------------------------------------------------
__global__ void __launch_bounds__(256)
softmax2048(const float* __restrict__ S, __nv_bfloat16* __restrict__ Ph,
            __nv_bfloat16* __restrict__ Pl)
{
    const float* p = S + (long long)blockIdx.x * 2048;
    const int t = threadIdx.x;

    float v[8];
    {
        const float4* p4 = reinterpret_cast<const float4*>(p + t * 8);
        float4 a = p4[0], b = p4[1];
        v[0] = a.x; v[1] = a.y; v[2] = a.z; v[3] = a.w;
        v[4] = b.x; v[5] = b.y; v[6] = b.z; v[7] = b.w;
    }

    float m = v[0];
#pragma unroll
    for (int i = 1; i < 8; i++) m = fmaxf(m, v[i]);

    __shared__ float red[8];
#pragma unroll
    for (int o = 16; o > 0; o >>= 1) m = fmaxf(m, __shfl_xor_sync(0xffffffffu, m, o));
    if ((t & 31) == 0) red[t >> 5] = m;
    __syncthreads();
    if (t < 32) {
        float mm = (t < 8) ? red[t] : -3.4e38f;
#pragma unroll
        for (int o = 4; o > 0; o >>= 1) mm = fmaxf(mm, __shfl_xor_sync(0xffffffffu, mm, o));
        if (t == 0) red[0] = mm;
    }
    __syncthreads();
    m = red[0];
    __syncthreads();

    float s = 0.f;
#pragma unroll
    for (int i = 0; i < 8; i++) { v[i] = __expf(v[i] - m); s += v[i]; }
#pragma unroll
    for (int o = 16; o > 0; o >>= 1) s += __shfl_xor_sync(0xffffffffu, s, o);
    if ((t & 31) == 0) red[t >> 5] = s;
    __syncthreads();
    if (t < 32) {
        float ss = (t < 8) ? red[t] : 0.f;
#pragma unroll
        for (int o = 4; o > 0; o >>= 1) ss += __shfl_xor_sync(0xffffffffu, ss, o);
        if (t == 0) red[0] = ss;
    }
    __syncthreads();
    const float inv = 1.f / red[0];

    __nv_bfloat162* oh =
        reinterpret_cast<__nv_bfloat162*>(Ph + (long long)blockIdx.x * 2048 + t * 8);
    __nv_bfloat162* ol =
        reinterpret_cast<__nv_bfloat162*>(Pl + (long long)blockIdx.x * 2048 + t * 8);
#pragma unroll
    for (int i = 0; i < 4; i++) {
        __nv_bfloat162 hh, ll;
        split2(v[i * 2] * inv, v[i * 2 + 1] * inv, hh, ll);
        oh[i] = hh;
        ol[i] = ll;
    }
}

// ---------------------------------------------------------------------------
extern "C" void kernel_launch(void* const* d_in, const int* in_sizes, int n_in,
                              void* d_out, int out_size)
{
    (void)in_sizes; (void)n_in; (void)out_size;

    const float* x   = (const float*)d_in[0];
    const float* y   = (const float*)d_in[1];
    const float* Wq1 = (const float*)d_in[2];
    const float* bq1 = (const float*)d_in[3];
    const float* Wk1 = (const float*)d_in[4];
    const float* bk1 = (const float*)d_in[5];
    const float* Wv1 = (const float*)d_in[6];
    const float* bv1 = (const float*)d_in[7];
    const float* Wq2 = (const float*)d_in[8];
    const float* bq2 = (const float*)d_in[9];
    const float* Wk2 = (const float*)d_in[10];
    const float* bk2 = (const float*)d_in[11];
    const float* Wv2 = (const float*)d_in[12];
    const float* bv2 = (const float*)d_in[13];
    const float* w1  = (const float*)d_in[14];
    const float* w2  = (const float*)d_in[15];
    float* out = (float*)d_out;

    __nv_bfloat16 *xyh, *xyl, *w1h, *w1l, *w2h, *w2l;
    __nv_bfloat16 *Q1h, *Q1l, *K1h, *K1l, *VT1h, *VT1l, *Ph, *Pl;
    __nv_bfloat16 *Th, *Tl, *Q2h, *Q2l, *K2h, *K2l, *VT2h, *VT2l;
    float *S, *b1c, *b2c;
    cudaGetSymbolAddress((void**)&xyh, g_xyh);   cudaGetSymbolAddress((void**)&xyl, g_xyl);
    cudaGetSymbolAddress((void**)&w1h, g_w1h);   cudaGetSymbolAddress((void**)&w1l, g_w1l);
    cudaGetSymbolAddress((void**)&w2h, g_w2h);   cudaGetSymbolAddress((void**)&w2l, g_w2l);
    cudaGetSymbolAddress((void**)&b1c, g_b1);    cudaGetSymbolAddress((void**)&b2c, g_b2);
    cudaGetSymbolAddress((void**)&Q1h, g_Q1h);   cudaGetSymbolAddress((void**)&Q1l, g_Q1l);
    cudaGetSymbolAddress((void**)&K1h, g_K1h);   cudaGetSymbolAddress((void**)&K1l, g_K1l);
    cudaGetSymbolAddress((void**)&VT1h, g_VT1h); cudaGetSymbolAddress((void**)&VT1l, g_VT1l);
    cudaGetSymbolAddress((void**)&S, g_S);
    cudaGetSymbolAddress((void**)&Ph, g_Ph);     cudaGetSymbolAddress((void**)&Pl, g_Pl);
    cudaGetSymbolAddress((void**)&Th, g_Th);     cudaGetSymbolAddress((void**)&Tl, g_Tl);
    cudaGetSymbolAddress((void**)&Q2h, g_Q2h);   cudaGetSymbolAddress((void**)&Q2l, g_Q2l);
    cudaGetSymbolAddress((void**)&K2h, g_K2h);   cudaGetSymbolAddress((void**)&K2l, g_K2l);
    cudaGetSymbolAddress((void**)&VT2h, g_VT2h); cudaGetSymbolAddress((void**)&VT2l, g_VT2l);

    cudaFuncSetAttribute(gemm_bf3<512, 3>,  cudaFuncAttributeMaxDynamicSharedMemorySize, SMEM_BYTES);
    cudaFuncSetAttribute(gemm_bf3<512, 0>,  cudaFuncAttributeMaxDynamicSharedMemorySize, SMEM_BYTES);
    cudaFuncSetAttribute(gemm_bf3<2048, 4>, cudaFuncAttributeMaxDynamicSharedMemorySize, SMEM_BYTES);
    cudaFuncSetAttribute(gemm_bf3<1024, 3>, cudaFuncAttributeMaxDynamicSharedMemorySize, SMEM_BYTES);
    cudaFuncSetAttribute(gemm_bf3<1024, 0>, cudaFuncAttributeMaxDynamicSharedMemorySize, SMEM_BYTES);
    cudaFuncSetAttribute(gemm_bf3<2048, 0>, cudaFuncAttributeMaxDynamicSharedMemorySize, SMEM_BYTES);

    const dim3 blk(256);
    const dim3 gblk(128);
    const long long HX = 8192LL * 512;
    const float* NF = nullptr;

    // 1: split x,y
    split_xy<<<(int)((HX / 2 + 255) / 256), blk>>>(x, y, xyh, xyl, HX / 4);
    // 2,3: split+concat weights/biases
    split_w3<<<(3 * 512 * 512 / 4 + 255) / 256, blk>>>(Wq1, Wk1, Wv1, bq1, bk1, bv1,
                                                       w1h, w1l, b1c, 512, 512);
    split_w3<<<(3 * 1024 * 1024 / 4 + 255) / 256, blk>>>(Wq2, Wk2, Wv2, bq2, bk2, bv2,
                                                         w2h, w2l, b2c, 1024, 1024);

    // 4: QKV1 fused (M=16384, N=1536, K=512), routing epilogue
    dim3 g1(1536 / 128, 16384 / 128);
    gemm_bf3<512, 3><<<g1, gblk, SMEM_BYTES>>>(xyh, xyl, w1h, w1l, b1c,
                                       nullptr, Q1h, Q1l, K1h, K1l, VT1h, VT1l,
                                       NF, NF, NF, NF,
                                       16384, 1536, 0, 0, 0, 512);

    // 5: scores1 (z=8)
    dim3 gs1(2048 / 128, 2048 / 128, 8);
    gemm_bf3<512, 0><<<gs1, gblk, SMEM_BYTES>>>(Q1h, Q1l, K1h, K1l, nullptr,
                                        S, nullptr, nullptr, nullptr, nullptr,
                                        nullptr, nullptr, NF, NF, NF, NF,
                                        2048, 2048,
                                        2048LL * 512, 2048LL * 512, 2048LL * 2048, 0);
    // 6: softmax1
    softmax2048<<<16384, blk>>>(S, Ph, Pl);
    // 7: PV1 + build_temp fused -> T planes
    dim3 gp1(512 / 128, 2048 / 128, 8);
    gemm_bf3<2048, 4><<<gp1, gblk, SMEM_BYTES>>>(Ph, Pl, VT1h, VT1l, nullptr,
                                        nullptr, Th, Tl, nullptr, nullptr,
                                        nullptr, nullptr, x, y, w1, w2,
                                        2048, 512,
                                        2048LL * 2048, 512LL * 2048, 0, 0);

    // 8: QKV2 fused (M=8192, N=3072, K=1024)
    dim3 g2(3072 / 128, 8192 / 128);
    gemm_bf3<1024, 3><<<g2, gblk, SMEM_BYTES>>>(Th, Tl, w2h, w2l, b2c,
                                       nullptr, Q2h, Q2l, K2h, K2l, VT2h, VT2l,
                                       NF, NF, NF, NF,
                                       8192, 3072, 0, 0, 0, 1024);

    // 9: scores2 (z=4)
    dim3 gs2(2048 / 128, 2048 / 128, 4);
    gemm_bf3<1024, 0><<<gs2, gblk, SMEM_BYTES>>>(Q2h, Q2l, K2h, K2l, nullptr,
                                        S, nullptr, nullptr, nullptr, nullptr,
                                        nullptr, nullptr, NF, NF, NF, NF,
                                        2048, 2048,
                                        2048LL * 1024, 2048LL * 1024, 2048LL * 2048, 0);
    // 10: softmax2
    softmax2048<<<8192, blk>>>(S, Ph, Pl);
    // 11: PV2 -> out (fp32)
    dim3 gp2(1024 / 128, 2048 / 128, 4);
    gemm_bf3<2048, 0><<<gp2, gblk, SMEM_BYTES>>>(Ph, Pl, VT2h, VT2l, nullptr,
                                        out, nullptr, nullptr, nullptr, nullptr,
                                        nullptr, nullptr, NF, NF, NF, NF,
                                        2048, 1024,
                                        2048LL * 2048, 1024LL * 2048, 2048LL * 1024, 0);
}

// round 12
// speedup vs baseline: 1.0755x; 1.0755x over previous
#include <cuda_runtime.h>
#include <cuda_bf16.h>
#include <cstdint>

// ===========================================================================
// Cross-attention. All GEMMs: bf16 split-precision x3 HMMA (fp32 acc).
// 128x64 block tile, 4 warps (warp 64x32), cp.async 3-stage pipeline,
// __launch_bounds__(128,3) -> 3 CTAs/SM. Templated <K, MODE>; cp.async burst
// deferred past pass-hh so LDGSTS doesn't collide with chunk-start LDSMs.
// ===========================================================================

// ---------------- helpers ----------------
__device__ __forceinline__ uint32_t smem_u32(const void* p) {
    uint32_t a;
    asm("{ .reg .u64 t; cvta.to.shared.u64 t, %1; cvt.u32.u64 %0, t; }"
        : "=r"(a) : "l"(p));
    return a;
}
__device__ __forceinline__ void ldsm_x4(uint32_t* r, uint32_t addr) {
    asm volatile("ldmatrix.sync.aligned.m8n8.x4.shared.b16 {%0,%1,%2,%3}, [%4];"
                 : "=r"(r[0]), "=r"(r[1]), "=r"(r[2]), "=r"(r[3]) : "r"(addr));
}
__device__ __forceinline__ void mma16816(float* d, const uint32_t* a,
                                         uint32_t b0, uint32_t b1) {
    asm volatile(
        "mma.sync.aligned.m16n8k16.row.col.f32.bf16.bf16.f32 "
        "{%0,%1,%2,%3}, {%4,%5,%6,%7}, {%8,%9}, {%0,%1,%2,%3};"
        : "+f"(d[0]), "+f"(d[1]), "+f"(d[2]), "+f"(d[3])
        : "r"(a[0]), "r"(a[1]), "r"(a[2]), "r"(a[3]), "r"(b0), "r"(b1));
}
__device__ __forceinline__ void cp16(uint32_t s, const void* g) {
    asm volatile("cp.async.cg.shared.global [%0], [%1], 16;" :: "r"(s), "l"(g));
}
__device__ __forceinline__ void split2(float v0, float v1,
                                       __nv_bfloat162& hh, __nv_bfloat162& ll) {
    __nv_bfloat16 h0 = __float2bfloat16(v0);
    __nv_bfloat16 h1 = __float2bfloat16(v1);
    hh.x = h0; hh.y = h1;
    ll.x = __float2bfloat16(v0 - __bfloat162float(h0));
    ll.y = __float2bfloat16(v1 - __bfloat162float(h1));
}

// ---------------- scratch (static device memory; bf16 hi/lo planes) -------
__device__ __nv_bfloat16 g_xyh[16384LL * 512], g_xyl[16384LL * 512];
__device__ __nv_bfloat16 g_w1h[1536 * 512],   g_w1l[1536 * 512];    // [q;k;v]
__device__ __nv_bfloat16 g_w2h[3072 * 1024],  g_w2l[3072 * 1024];   // [q;k;v]
__device__ float         g_b1[1536], g_b2[3072];
__device__ __nv_bfloat16 g_Q1h[16384LL * 512], g_Q1l[16384LL * 512];
__device__ __nv_bfloat16 g_K1h[16384LL * 512], g_K1l[16384LL * 512];
__device__ __nv_bfloat16 g_VT1h[16384LL * 512], g_VT1l[16384LL * 512]; // [8][512][2048]
__device__ float         g_S [8LL * 2048 * 2048];
__device__ __nv_bfloat16 g_Ph[8LL * 2048 * 2048], g_Pl[8LL * 2048 * 2048];
__device__ __nv_bfloat16 g_Th[8192LL * 1024], g_Tl[8192LL * 1024];
__device__ __nv_bfloat16 g_Q2h[8192LL * 1024], g_Q2l[8192LL * 1024];
__device__ __nv_bfloat16 g_K2h[8192LL * 1024], g_K2l[8192LL * 1024];
__device__ __nv_bfloat16 g_VT2h[8192LL * 1024], g_VT2l[8192LL * 1024]; // [4][1024][2048]

// Stage (24KB): Ah +0 (8K), Al +8192, Bh +16384 (4K), Bl +20480. 3 stages.
static constexpr int STG = 24576;
static constexpr int SMEM_BYTES = 3 * STG;   // 73728 -> 3 CTAs/SM

// ===========================================================================
// NT GEMM: C[M,N] = (Ah+Al)[M,K]*(Bh+Bl)[N,K]^T, 3-pass bf16 HMMA, fp32 acc.
// Block tile 128x64, warp tile 64x32. Template K (compile-time addressing),
// MODE: 0 fp32 out; 3 QKV routing; 4 PV1+build_temp.
// ===========================================================================
template<int K, int MODE>
__global__ void __launch_bounds__(128, 3)
gemm_bf3(const __nv_bfloat16* __restrict__ Ah, const __nv_bfloat16* __restrict__ Al,
         const __nv_bfloat16* __restrict__ Bh, const __nv_bfloat16* __restrict__ Bl,
         const float* __restrict__ bias,
         float* __restrict__ Cf,
         __nv_bfloat16* __restrict__ P0h, __nv_bfloat16* __restrict__ P0l,
         __nv_bfloat16* __restrict__ P1h, __nv_bfloat16* __restrict__ P1l,
         __nv_bfloat16* __restrict__ P2h, __nv_bfloat16* __restrict__ P2l,
         const float* __restrict__ rx, const float* __restrict__ ry,
         const float* __restrict__ rw1, const float* __restrict__ rw2,
         int M, int N,
         long long sA, long long sB, long long sC,
         int segN)
{
    extern __shared__ char smem[];
    const uint32_t sb = smem_u32(smem);
    const int tid = threadIdx.x;
    const int lane = tid & 31;
    const int wid = tid >> 5;            // 0..3
    const int z = blockIdx.z;

    const int m0 = blockIdx.y * 128;
    const int n0 = blockIdx.x * 64;
    const int m0w = (wid & 1) * 64;
    const int n0w = (wid >> 1) * 32;

    // cp.async: 128 threads, 12 x 16B each per chunk (A 128 rows, B 64 rows)
    const int r0 = tid >> 2, c0 = tid & 3;             // 32 rows x 4 col-groups
    const uint32_t soff0 = (uint32_t)r0 * 64 + (uint32_t)((c0 ^ ((r0 >> 1) & 3)) << 4);
    const __nv_bfloat16* pAh = Ah + (long long)z * sA + (long long)(m0 + r0) * K + c0 * 8;
    const __nv_bfloat16* pAl = Al + (long long)z * sA + (long long)(m0 + r0) * K + c0 * 8;
    const __nv_bfloat16* pBh = Bh + (long long)z * sB + (long long)(n0 + r0) * K + c0 * 8;
    const __nv_bfloat16* pBl = Bl + (long long)z * sB + (long long)(n0 + r0) * K + c0 * 8;
    if (Cf) Cf += (long long)z * sC;

    constexpr int RS = 32 * K;           // 32-row stride (elements), compile-time

    uint32_t iaddr = sb + soff0;                    // rotating cp.async dst
    const uint32_t ilim = sb + soff0 + 3 * STG;

#define ISSUE() do {                                                            \
    cp16(iaddr + 0,     pAh);                                                   \
    cp16(iaddr + 2048,  pAh + RS);                                              \
    cp16(iaddr + 4096,  pAh + 2 * RS);                                          \
    cp16(iaddr + 6144,  pAh + 3 * RS);                                          \
    cp16(iaddr + 8192,  pAl);                                                   \
    cp16(iaddr + 10240, pAl + RS);                                              \
    cp16(iaddr + 12288, pAl + 2 * RS);                                          \
    cp16(iaddr + 14336, pAl + 3 * RS);                                          \
    cp16(iaddr + 16384, pBh);                                                   \
    cp16(iaddr + 18432, pBh + RS);                                              \
    cp16(iaddr + 20480, pBl);                                                   \
    cp16(iaddr + 22528, pBl + RS);                                              \
    asm volatile("cp.async.commit_group;" ::: "memory");                        \
    pAh += 32; pAl += 32; pBh += 32; pBl += 32;                                 \
    iaddr += STG; if (iaddr == ilim) iaddr -= 3 * STG;                          \
} while (0)

    float acc[4][4][4];
#pragma unroll
    for (int i = 0; i < 4; i++)
#pragma unroll
        for (int j = 0; j < 4; j++)
#pragma unroll
            for (int k = 0; k < 4; k++) acc[i][j][k] = 0.f;

    // LDSM base addresses (stage 0, kstep 0); mf/q/plane deltas are immediates
    const int kc0 = lane >> 4;
    const int arow0 = m0w + (lane & 15);
    const int brow0 = n0w + (lane & 15);
    uint32_t a0 = sb + (uint32_t)arow0 * 64
                + (uint32_t)((kc0 ^ ((arow0 >> 1) & 3)) << 4);
    uint32_t b0 = sb + 16384 + (uint32_t)brow0 * 64
                + (uint32_t)((kc0 ^ ((brow0 >> 1) & 3)) << 4);
    const uint32_t alim = a0 + 3 * STG;

    constexpr int nch = K >> 5;
    ISSUE(); ISSUE();

#pragma unroll 1
    for (int ch = 0; ch < nch; ch++) {
        asm volatile("cp.async.wait_group 1;" ::: "memory");
        __syncthreads();

#pragma unroll
        for (int kstep = 0; kstep < 2; kstep++) {
            const uint32_t ax = a0 ^ ((uint32_t)kstep << 5);
            const uint32_t bx = b0 ^ ((uint32_t)kstep << 5);
            uint32_t aH[4][4], aL[4][4], bh[2][4], bl[2][4];
            // A-hi + B-hi; pass hh
#pragma unroll
            for (int mf = 0; mf < 4; mf++)
                ldsm_x4(aH[mf], ax + mf * 1024);
#pragma unroll
            for (int q = 0; q < 2; q++)
                ldsm_x4(bh[q], bx + q * 1024);
#pragma unroll
            for (int mf = 0; mf < 4; mf++)
#pragma unroll
                for (int q = 0; q < 2; q++) {
                    mma16816(acc[mf][q * 2 + 0], aH[mf], bh[q][0], bh[q][2]);
                    mma16816(acc[mf][q * 2 + 1], aH[mf], bh[q][1], bh[q][3]);
                }
            // deferred cp.async burst: LSU now idle while MMAs drain
            if (kstep == 0 && ch + 2 < nch) ISSUE();
            // B-lo; pass hl
#pragma unroll
            for (int q = 0; q < 2; q++)
                ldsm_x4(bl[q], bx + 4096 + q * 1024);
#pragma unroll
            for (int mf = 0; mf < 4; mf++)
#pragma unroll
                for (int q = 0; q < 2; q++) {
                    mma16816(acc[mf][q * 2 + 0], aH[mf], bl[q][0], bl[q][2]);
                    mma16816(acc[mf][q * 2 + 1], aH[mf], bl[q][1], bl[q][3]);
                }
            // A-lo; pass lh
#pragma unroll
            for (int mf = 0; mf < 4; mf++)
                ldsm_x4(aL[mf], ax + 8192 + mf * 1024);
#pragma unroll
            for (int mf = 0; mf < 4; mf++)
#pragma unroll
                for (int q = 0; q < 2; q++) {
                    mma16816(acc[mf][q * 2 + 0], aL[mf], bh[q][0], bh[q][2]);
                    mma16816(acc[mf][q * 2 + 1], aL[mf], bh[q][1], bh[q][3]);
                }
        }
        a0 += STG; b0 += STG;
        if (a0 == alim) { a0 -= 3 * STG; b0 -= 3 * STG; }
    }
#undef ISSUE

    // ---- epilogue ----
    const int gr = lane >> 2;
    const int gc = (lane & 3) * 2;

    if (MODE == 0) {
#pragma unroll
        for (int mf = 0; mf < 4; mf++)
#pragma unroll
            for (int nf = 0; nf < 4; nf++) {
                const int row = m0 + m0w + mf * 16 + gr;
                const int col = n0 + n0w + nf * 8 + gc;
                float b0f = 0.f, b1f = 0.f;
                if (bias) { b0f = bias[col]; b1f = bias[col + 1]; }
                float2 v0 = make_float2(acc[mf][nf][0] + b0f, acc[mf][nf][1] + b1f);
                float2 v1 = make_float2(acc[mf][nf][2] + b0f, acc[mf][nf][3] + b1f);
                *reinterpret_cast<float2*>(Cf + (long long)row * N + col) = v0;
                *reinterpret_cast<float2*>(Cf + (long long)(row + 8) * N + col) = v1;
            }
    } else if (MODE == 3) {
        const int seg = n0 / segN;              // CTA-uniform (64 | segN)
        const int cwbase = n0 - seg * segN + n0w;
        if (seg < 2) {
            __nv_bfloat16* Dh = seg ? P1h : P0h;
            __nv_bfloat16* Dl = seg ? P1l : P0l;
#pragma unroll
            for (int mf = 0; mf < 4; mf++)
#pragma unroll
                for (int nf = 0; nf < 4; nf++) {
                    const int row = m0 + m0w + mf * 16 + gr;
                    const int col = cwbase + nf * 8 + gc;
                    const float b0f = bias[n0 + n0w + nf * 8 + gc];
                    const float b1f = bias[n0 + n0w + nf * 8 + gc + 1];
#pragma unroll
                    for (int half = 0; half < 2; half++) {
                        __nv_bfloat162 hh, ll;
                        split2(acc[mf][nf][half * 2 + 0] + b0f,
                               acc[mf][nf][half * 2 + 1] + b1f, hh, ll);
                        const long long idx = (long long)(row + half * 8) * segN + col;
                        *reinterpret_cast<__nv_bfloat162*>(Dh + idx) = hh;
                        *reinterpret_cast<__nv_bfloat162*>(Dl + idx) = ll;
                    }
                }
        } else {
            // V: transposed VT layout, staged via smem (reuses pipeline smem)
            __syncthreads();
            float* tw = reinterpret_cast<float*>(smem) + wid * 2080;  // 32x65
#pragma unroll
            for (int mf = 0; mf < 4; mf++)
#pragma unroll
                for (int nf = 0; nf < 4; nf++) {
                    const int rl = mf * 16 + gr;
                    const int cl = nf * 8 + gc;
                    tw[cl * 65 + rl]           = acc[mf][nf][0];
                    tw[(cl + 1) * 65 + rl]     = acc[mf][nf][1];
                    tw[cl * 65 + rl + 8]       = acc[mf][nf][2];
                    tw[(cl + 1) * 65 + rl + 8] = acc[mf][nf][3];
                }
            __syncwarp();
            const int g0 = m0 + m0w;
            const long long basev =
                (long long)(g0 >> 11) * segN * 2048 + (g0 & 2047);
#pragma unroll 4
            for (int c = 0; c < 32; c++) {
                const int colg = cwbase + c;
                const float bb = bias[n0 + n0w + c];
                const float v0 = tw[c * 65 + lane * 2] + bb;
                const float v1 = tw[c * 65 + lane * 2 + 1] + bb;
                __nv_bfloat162 hh, ll;
                split2(v0, v1, hh, ll);
                const long long idx = basev + (long long)colg * 2048 + lane * 2;
                *reinterpret_cast<__nv_bfloat162*>(P2h + idx) = hh;
                *reinterpret_cast<__nv_bfloat162*>(P2l + idx) = ll;
            }
        }
    } else {
        // MODE 4: PV1 + build_temp fused -> T planes (N=512)
        const float w1v = rw1[0], w2v = rw2[0];
#pragma unroll
        for (int mf = 0; mf < 4; mf++)
#pragma unroll
            for (int nf = 0; nf < 4; nf++) {
                const int col = n0 + n0w + nf * 8 + gc;
#pragma unroll
                for (int half = 0; half < 2; half++) {
                    const int row = m0 + m0w + mf * 16 + gr + half * 8;
                    const int grow = z * 2048 + row;
                    long long tok; int tcol; float2 res;
                    if (grow < 8192) {
                        tok = grow; tcol = col;
                        float2 yy = *reinterpret_cast<const float2*>(
                            ry + tok * 512 + col);
                        res.x = yy.x * w2v; res.y = yy.y * w2v;
                    } else {
                        tok = grow - 8192; tcol = col + 512;
                        float2 xx = *reinterpret_cast<const float2*>(
                            rx + tok * 512 + col);
                        res.x = xx.x * w1v; res.y = xx.y * w1v;
                    }
                    __nv_bfloat162 hh, ll;
                    split2(acc[mf][nf][half * 2 + 0] + res.x,
                           acc[mf][nf][half * 2 + 1] + res.y, hh, ll);
                    const long long idx = tok * 1024 + tcol;
                    *reinterpret_cast<__nv_bfloat162*>(P0h + idx) = hh;
                    *reinterpret_cast<__nv_bfloat162*>(P0l + idx) = ll;
                }
            }
    }
}

// ---------------------------------------------------------------------------
// split x and y fp32 -> stacked bf16 hi/lo planes (float4 granularity)
// ---------------------------------------------------------------------------
__global__ void __launch_bounds__(256)
split_xy(const float* __restrict__ x, const float* __restrict__ y,
         __nv_bfloat16* __restrict__ h, __nv_bfloat16* __restrict__ l,
         long long n4half)
{
    long long i = (long long)blockIdx.x * 256 + threadIdx.x;
    if (i >= 2 * n4half) return;
    const float* s = (i < n4half) ? x : y;
    const long long off = (i < n4half) ? i : i - n4half;
    float4 v = reinterpret_cast<const float4*>(s)[off];
    __nv_bfloat162 h0, l0, h1, l1;
    split2(v.x, v.y, h0, l0);
    split2(v.z, v.w, h1, l1);
    uint2 hh, ll;
    hh.x = *reinterpret_cast<uint32_t*>(&h0); hh.y = *reinterpret_cast<uint32_t*>(&h1);
    ll.x = *reinterpret_cast<uint32_t*>(&l0); ll.y = *reinterpret_cast<uint32_t*>(&l1);
    reinterpret_cast<uint2*>(h)[i] = hh;
    reinterpret_cast<uint2*>(l)[i] = ll;
}

// ---------------------------------------------------------------------------
// split 3 weight matrices into concatenated plane pair + concat biases
// ---------------------------------------------------------------------------
__global__ void __launch_bounds__(256)
split_w3(const float* __restrict__ s0, const float* __restrict__ s1,
         const float* __restrict__ s2,
         const float* __restrict__ b0, const float* __restrict__ b1,
         const float* __restrict__ b2,
         __nv_bfloat16* __restrict__ h, __nv_bfloat16* __restrict__ l,
         float* __restrict__ bcat, int rows, int K)
{
    const long long seglen = (long long)rows * K / 4;   // float4 per segment
    long long i = (long long)blockIdx.x * 256 + threadIdx.x;
    if (i < 3 * seglen) {
        const int seg = (int)(i / seglen);
        const long long off = i - (long long)seg * seglen;
        const float* s = (seg == 0) ? s0 : (seg == 1) ? s1 : s2;
        float4 v = reinterpret_cast<const float4*>(s)[off];
        __nv_bfloat162 h0, l0, h1, l1;
        split2(v.x, v.y, h0, l0);
        split2(v.z, v.w, h1, l1);
        uint2 hh, ll;
        hh.x = *reinterpret_cast<uint32_t*>(&h0); hh.y = *reinterpret_cast<uint32_t*>(&h1);
        ll.x = *reinterpret_cast<uint32_t*>(&l0); ll.y = *reinterpret_cast<uint32_t*>(&l1);
        reinterpret_cast<uint2*>(h)[i] = hh;
        reinterpret_cast<uint2*>(l)[i] = ll;
    }
    const long long t = (long long)blockIdx.x * 256 + threadIdx.x;
    if (t < 3 * rows) {
        const int seg = (int)(t / rows);
        const int off = (int)(t - seg * rows);
        bcat[t] = (seg == 0) ? b0[off] : (seg == 1) ? b1[off] : b2[off];
    }
}

// ---------------------------------------------------------------------------
// Row softmax over 2048 cols; fp32 in, split bf16 hi/lo out. Block = row.
// ---------------------------------------------------------------------------
__global__ void __launch_bounds__(256)
softmax2048(const float* __restrict__ S, __nv_bfloat16* __restrict__ Ph,
            __nv_bfloat16* __restrict__ Pl)
{
    const float* p = S + (long long)blockIdx.x * 2048;
    const int t = threadIdx.x;

    float v[8];
    {
        const float4* p4 = reinterpret_cast<const float4*>(p + t * 8);
        float4 a = p4[0], b = p4[1];
        v[0] = a.x; v[1] = a.y; v[2] = a.z; v[3] = a.w;
        v[4] = b.x; v[5] = b.y; v[6] = b.z; v[7] = b.w;
    }

    float m = v[0];
#pragma unroll
    for (int i = 1; i < 8; i++) m = fmaxf(m, v[i]);

    __shared__ float red[8];
#pragma unroll
    for (int o = 16; o > 0; o >>= 1) m = fmaxf(m, __shfl_xor_sync(0xffffffffu, m, o));
    if ((t & 31) == 0) red[t >> 5] = m;
    __syncthreads();
    if (t < 32) {
        float mm = (t < 8) ? red[t] : -3.4e38f;
#pragma unroll
        for (int o = 4; o > 0; o >>= 1) mm = fmaxf(mm, __shfl_xor_sync(0xffffffffu, mm, o));
        if (t == 0) red[0] = mm;
    }
    __syncthreads();
    m = red[0];
    __syncthreads();

    float s = 0.f;
#pragma unroll
    for (int i = 0; i < 8; i++) { v[i] = __expf(v[i] - m); s += v[i]; }
#pragma unroll
    for (int o = 16; o > 0; o >>= 1) s += __shfl_xor_sync(0xffffffffu, s, o);
    if ((t & 31) == 0) red[t >> 5] = s;
    __syncthreads();
    if (t < 32) {
        float ss = (t < 8) ? red[t] : 0.f;
#pragma unroll
        for (int o = 4; o > 0; o >>= 1) ss += __shfl_xor_sync(0xffffffffu, ss, o);
        if (t == 0) red[0] = ss;
    }
    __syncthreads();
    const float inv = 1.f / red[0];

    __nv_bfloat162* oh =
        reinterpret_cast<__nv_bfloat162*>(Ph + (long long)blockIdx.x * 2048 + t * 8);
    __nv_bfloat162* ol =
        reinterpret_cast<__nv_bfloat162*>(Pl + (long long)blockIdx.x * 2048 + t * 8);
#pragma unroll
    for (int i = 0; i < 4; i++) {
        __nv_bfloat162 hh, ll;
        split2(v[i * 2] * inv, v[i * 2 + 1] * inv, hh, ll);
        oh[i] = hh;
        ol[i] = ll;
    }
}

// ---------------------------------------------------------------------------
extern "C" void kernel_launch(void* const* d_in, const int* in_sizes, int n_in,
                              void* d_out, int out_size)
{
    (void)in_sizes; (void)n_in; (void)out_size;

    const float* x   = (const float*)d_in[0];
    const float* y   = (const float*)d_in[1];
    const float* Wq1 = (const float*)d_in[2];
    const float* bq1 = (const float*)d_in[3];
    const float* Wk1 = (const float*)d_in[4];
    const float* bk1 = (const float*)d_in[5];
    const float* Wv1 = (const float*)d_in[6];
    const float* bv1 = (const float*)d_in[7];
    const float* Wq2 = (const float*)d_in[8];
    const float* bq2 = (const float*)d_in[9];
    const float* Wk2 = (const float*)d_in[10];
    const float* bk2 = (const float*)d_in[11];
    const float* Wv2 = (const float*)d_in[12];
    const float* bv2 = (const float*)d_in[13];
    const float* w1  = (const float*)d_in[14];
    const float* w2  = (const float*)d_in[15];
    float* out = (float*)d_out;

    __nv_bfloat16 *xyh, *xyl, *w1h, *w1l, *w2h, *w2l;
    __nv_bfloat16 *Q1h, *Q1l, *K1h, *K1l, *VT1h, *VT1l, *Ph, *Pl;
    __nv_bfloat16 *Th, *Tl, *Q2h, *Q2l, *K2h, *K2l, *VT2h, *VT2l;
    float *S, *b1c, *b2c;
    cudaGetSymbolAddress((void**)&xyh, g_xyh);   cudaGetSymbolAddress((void**)&xyl, g_xyl);
    cudaGetSymbolAddress((void**)&w1h, g_w1h);   cudaGetSymbolAddress((void**)&w1l, g_w1l);
    cudaGetSymbolAddress((void**)&w2h, g_w2h);   cudaGetSymbolAddress((void**)&w2l, g_w2l);
    cudaGetSymbolAddress((void**)&b1c, g_b1);    cudaGetSymbolAddress((void**)&b2c, g_b2);
    cudaGetSymbolAddress((void**)&Q1h, g_Q1h);   cudaGetSymbolAddress((void**)&Q1l, g_Q1l);
    cudaGetSymbolAddress((void**)&K1h, g_K1h);   cudaGetSymbolAddress((void**)&K1l, g_K1l);
    cudaGetSymbolAddress((void**)&VT1h, g_VT1h); cudaGetSymbolAddress((void**)&VT1l, g_VT1l);
    cudaGetSymbolAddress((void**)&S, g_S);
    cudaGetSymbolAddress((void**)&Ph, g_Ph);     cudaGetSymbolAddress((void**)&Pl, g_Pl);
    cudaGetSymbolAddress((void**)&Th, g_Th);     cudaGetSymbolAddress((void**)&Tl, g_Tl);
    cudaGetSymbolAddress((void**)&Q2h, g_Q2h);   cudaGetSymbolAddress((void**)&Q2l, g_Q2l);
    cudaGetSymbolAddress((void**)&K2h, g_K2h);   cudaGetSymbolAddress((void**)&K2l, g_K2l);
    cudaGetSymbolAddress((void**)&VT2h, g_VT2h); cudaGetSymbolAddress((void**)&VT2l, g_VT2l);

    cudaFuncSetAttribute(gemm_bf3<512, 3>,  cudaFuncAttributeMaxDynamicSharedMemorySize, SMEM_BYTES);
    cudaFuncSetAttribute(gemm_bf3<512, 0>,  cudaFuncAttributeMaxDynamicSharedMemorySize, SMEM_BYTES);
    cudaFuncSetAttribute(gemm_bf3<2048, 4>, cudaFuncAttributeMaxDynamicSharedMemorySize, SMEM_BYTES);
    cudaFuncSetAttribute(gemm_bf3<1024, 3>, cudaFuncAttributeMaxDynamicSharedMemorySize, SMEM_BYTES);
    cudaFuncSetAttribute(gemm_bf3<1024, 0>, cudaFuncAttributeMaxDynamicSharedMemorySize, SMEM_BYTES);
    cudaFuncSetAttribute(gemm_bf3<2048, 0>, cudaFuncAttributeMaxDynamicSharedMemorySize, SMEM_BYTES);

    const dim3 blk(256);
    const dim3 gblk(128);
    const long long HX = 8192LL * 512;
    const float* NF = nullptr;

    // 1: split x,y
    split_xy<<<(int)((HX / 2 + 255) / 256), blk>>>(x, y, xyh, xyl, HX / 4);
    // 2,3: split+concat weights/biases
    split_w3<<<(3 * 512 * 512 / 4 + 255) / 256, blk>>>(Wq1, Wk1, Wv1, bq1, bk1, bv1,
                                                       w1h, w1l, b1c, 512, 512);
    split_w3<<<(3 * 1024 * 1024 / 4 + 255) / 256, blk>>>(Wq2, Wk2, Wv2, bq2, bk2, bv2,
                                                         w2h, w2l, b2c, 1024, 1024);

    // 4: QKV1 fused (M=16384, N=1536, K=512), routing epilogue
    dim3 g1(1536 / 64, 16384 / 128);
    gemm_bf3<512, 3><<<g1, gblk, SMEM_BYTES>>>(xyh, xyl, w1h, w1l, b1c,
                                       nullptr, Q1h, Q1l, K1h, K1l, VT1h, VT1l,
                                       NF, NF, NF, NF,
                                       16384, 1536, 0, 0, 0, 512);

    // 5: scores1 (z=8)
    dim3 gs1(2048 / 64, 2048 / 128, 8);
    gemm_bf3<512, 0><<<gs1, gblk, SMEM_BYTES>>>(Q1h, Q1l, K1h, K1l, nullptr,
                                        S, nullptr, nullptr, nullptr, nullptr,
                                        nullptr, nullptr, NF, NF, NF, NF,
                                        2048, 2048,
                                        2048LL * 512, 2048LL * 512, 2048LL * 2048, 0);
    // 6: softmax1
    softmax2048<<<16384, blk>>>(S, Ph, Pl);
    // 7: PV1 + build_temp fused -> T planes
    dim3 gp1(512 / 64, 2048 / 128, 8);
    gemm_bf3<2048, 4><<<gp1, gblk, SMEM_BYTES>>>(Ph, Pl, VT1h, VT1l, nullptr,
                                        nullptr, Th, Tl, nullptr, nullptr,
                                        nullptr, nullptr, x, y, w1, w2,
                                        2048, 512,
                                        2048LL * 2048, 512LL * 2048, 0, 0);

    // 8: QKV2 fused (M=8192, N=3072, K=1024)
    dim3 g2(3072 / 64, 8192 / 128);
    gemm_bf3<1024, 3><<<g2, gblk, SMEM_BYTES>>>(Th, Tl, w2h, w2l, b2c,
                                       nullptr, Q2h, Q2l, K2h, K2l, VT2h, VT2l,
                                       NF, NF, NF, NF,
                                       8192, 3072, 0, 0, 0, 1024);

    // 9: scores2 (z=4)
    dim3 gs2(2048 / 64, 2048 / 128, 4);
    gemm_bf3<1024, 0><<<gs2, gblk, SMEM_BYTES>>>(Q2h, Q2l, K2h, K2l, nullptr,
                                        S, nullptr, nullptr, nullptr, nullptr,
                                        nullptr, nullptr, NF, NF, NF, NF,
                                        2048, 2048,
                                        2048LL * 1024, 2048LL * 1024, 2048LL * 2048, 0);
    // 10: softmax2
    softmax2048<<<8192, blk>>>(S, Ph, Pl);
    // 11: PV2 -> out (fp32)
    dim3 gp2(1024 / 64, 2048 / 128, 4);
    gemm_bf3<2048, 0><<<gp2, gblk, SMEM_BYTES>>>(Ph, Pl, VT2h, VT2l, nullptr,
                                        out, nullptr, nullptr, nullptr, nullptr,
                                        nullptr, nullptr, NF, NF, NF, NF,
                                        2048, 1024,
                                        2048LL * 2048, 1024LL * 2048, 2048LL * 1024, 0);
}

// round 13
// speedup vs baseline: 1.0762x; 1.0007x over previous
#include <cuda_runtime.h>
#include <cuda_bf16.h>
#include <cstdint>

// ===========================================================================
// Cross-attention. All GEMMs: bf16 split-precision x3 HMMA (fp32 acc).
// 128x64 block tile, 4 warps (warp 64x32), cp.async 3-stage pipeline,
// __launch_bounds__(128,3) -> 3 CTAs/SM. Templated <K, MODE>. All 12 LDSMs
// of a kstep issued as one front burst (asm volatile preserves order; burst
// maximizes LDSM MLP and overlaps crossbar with the 48-MMA block).
// ===========================================================================

// ---------------- helpers ----------------
__device__ __forceinline__ uint32_t smem_u32(const void* p) {
    uint32_t a;
    asm("{ .reg .u64 t; cvta.to.shared.u64 t, %1; cvt.u32.u64 %0, t; }"
        : "=r"(a) : "l"(p));
    return a;
}
__device__ __forceinline__ void ldsm_x4(uint32_t* r, uint32_t addr) {
    asm volatile("ldmatrix.sync.aligned.m8n8.x4.shared.b16 {%0,%1,%2,%3}, [%4];"
                 : "=r"(r[0]), "=r"(r[1]), "=r"(r[2]), "=r"(r[3]) : "r"(addr));
}
__device__ __forceinline__ void mma16816(float* d, const uint32_t* a,
                                         uint32_t b0, uint32_t b1) {
    asm volatile(
        "mma.sync.aligned.m16n8k16.row.col.f32.bf16.bf16.f32 "
        "{%0,%1,%2,%3}, {%4,%5,%6,%7}, {%8,%9}, {%0,%1,%2,%3};"
        : "+f"(d[0]), "+f"(d[1]), "+f"(d[2]), "+f"(d[3])
        : "r"(a[0]), "r"(a[1]), "r"(a[2]), "r"(a[3]), "r"(b0), "r"(b1));
}
__device__ __forceinline__ void cp16(uint32_t s, const void* g) {
    asm volatile("cp.async.cg.shared.global [%0], [%1], 16;" :: "r"(s), "l"(g));
}
__device__ __forceinline__ void split2(float v0, float v1,
                                       __nv_bfloat162& hh, __nv_bfloat162& ll) {
    __nv_bfloat16 h0 = __float2bfloat16(v0);
    __nv_bfloat16 h1 = __float2bfloat16(v1);
    hh.x = h0; hh.y = h1;
    ll.x = __float2bfloat16(v0 - __bfloat162float(h0));
    ll.y = __float2bfloat16(v1 - __bfloat162float(h1));
}

// ---------------- scratch (static device memory; bf16 hi/lo planes) -------
__device__ __nv_bfloat16 g_xyh[16384LL * 512], g_xyl[16384LL * 512];
__device__ __nv_bfloat16 g_w1h[1536 * 512],   g_w1l[1536 * 512];    // [q;k;v]
__device__ __nv_bfloat16 g_w2h[3072 * 1024],  g_w2l[3072 * 1024];   // [q;k;v]
__device__ float         g_b1[1536], g_b2[3072];
__device__ __nv_bfloat16 g_Q1h[16384LL * 512], g_Q1l[16384LL * 512];
__device__ __nv_bfloat16 g_K1h[16384LL * 512], g_K1l[16384LL * 512];
__device__ __nv_bfloat16 g_VT1h[16384LL * 512], g_VT1l[16384LL * 512]; // [8][512][2048]
__device__ float         g_S [8LL * 2048 * 2048];
__device__ __nv_bfloat16 g_Ph[8LL * 2048 * 2048], g_Pl[8LL * 2048 * 2048];
__device__ __nv_bfloat16 g_Th[8192LL * 1024], g_Tl[8192LL * 1024];
__device__ __nv_bfloat16 g_Q2h[8192LL * 1024], g_Q2l[8192LL * 1024];
__device__ __nv_bfloat16 g_K2h[8192LL * 1024], g_K2l[8192LL * 1024];
__device__ __nv_bfloat16 g_VT2h[8192LL * 1024], g_VT2l[8192LL * 1024]; // [4][1024][2048]

// Stage (24KB): Ah +0 (8K), Al +8192, Bh +16384 (4K), Bl +20480. 3 stages.
static constexpr int STG = 24576;
static constexpr int SMEM_BYTES = 3 * STG;   // 73728 -> 3 CTAs/SM

// ===========================================================================
// NT GEMM: C[M,N] = (Ah+Al)[M,K]*(Bh+Bl)[N,K]^T, 3-pass bf16 HMMA, fp32 acc.
// Block tile 128x64, warp tile 64x32. Template K (compile-time addressing),
// MODE: 0 fp32 out; 3 QKV routing; 4 PV1+build_temp.
// ===========================================================================
template<int K, int MODE>
__global__ void __launch_bounds__(128, 3)
gemm_bf3(const __nv_bfloat16* __restrict__ Ah, const __nv_bfloat16* __restrict__ Al,
         const __nv_bfloat16* __restrict__ Bh, const __nv_bfloat16* __restrict__ Bl,
         const float* __restrict__ bias,
         float* __restrict__ Cf,
         __nv_bfloat16* __restrict__ P0h, __nv_bfloat16* __restrict__ P0l,
         __nv_bfloat16* __restrict__ P1h, __nv_bfloat16* __restrict__ P1l,
         __nv_bfloat16* __restrict__ P2h, __nv_bfloat16* __restrict__ P2l,
         const float* __restrict__ rx, const float* __restrict__ ry,
         const float* __restrict__ rw1, const float* __restrict__ rw2,
         int M, int N,
         long long sA, long long sB, long long sC,
         int segN)
{
    extern __shared__ char smem[];
    const uint32_t sb = smem_u32(smem);
    const int tid = threadIdx.x;
    const int lane = tid & 31;
    const int wid = tid >> 5;            // 0..3
    const int z = blockIdx.z;

    const int m0 = blockIdx.y * 128;
    const int n0 = blockIdx.x * 64;
    const int m0w = (wid & 1) * 64;
    const int n0w = (wid >> 1) * 32;

    // cp.async: 128 threads, 12 x 16B each per chunk (A 128 rows, B 64 rows)
    const int r0 = tid >> 2, c0 = tid & 3;             // 32 rows x 4 col-groups
    const uint32_t soff0 = (uint32_t)r0 * 64 + (uint32_t)((c0 ^ ((r0 >> 1) & 3)) << 4);
    const __nv_bfloat16* pAh = Ah + (long long)z * sA + (long long)(m0 + r0) * K + c0 * 8;
    const __nv_bfloat16* pAl = Al + (long long)z * sA + (long long)(m0 + r0) * K + c0 * 8;
    const __nv_bfloat16* pBh = Bh + (long long)z * sB + (long long)(n0 + r0) * K + c0 * 8;
    const __nv_bfloat16* pBl = Bl + (long long)z * sB + (long long)(n0 + r0) * K + c0 * 8;
    if (Cf) Cf += (long long)z * sC;

    constexpr int RS = 32 * K;           // 32-row stride (elements), compile-time

    uint32_t iaddr = sb + soff0;                    // rotating cp.async dst
    const uint32_t ilim = sb + soff0 + 3 * STG;

#define ISSUE() do {                                                            \
    cp16(iaddr + 0,     pAh);                                                   \
    cp16(iaddr + 2048,  pAh + RS);                                              \
    cp16(iaddr + 4096,  pAh + 2 * RS);                                          \
    cp16(iaddr + 6144,  pAh + 3 * RS);                                          \
    cp16(iaddr + 8192,  pAl);                                                   \
    cp16(iaddr + 10240, pAl + RS);                                              \
    cp16(iaddr + 12288, pAl + 2 * RS);                                          \
    cp16(iaddr + 14336, pAl + 3 * RS);                                          \
    cp16(iaddr + 16384, pBh);                                                   \
    cp16(iaddr + 18432, pBh + RS);                                              \
    cp16(iaddr + 20480, pBl);                                                   \
    cp16(iaddr + 22528, pBl + RS);                                              \
    asm volatile("cp.async.commit_group;" ::: "memory");                        \
    pAh += 32; pAl += 32; pBh += 32; pBl += 32;                                 \
    iaddr += STG; if (iaddr == ilim) iaddr -= 3 * STG;                          \
} while (0)

    float acc[4][4][4];
#pragma unroll
    for (int i = 0; i < 4; i++)
#pragma unroll
        for (int j = 0; j < 4; j++)
#pragma unroll
            for (int k = 0; k < 4; k++) acc[i][j][k] = 0.f;

    // LDSM base addresses (stage 0, kstep 0); mf/q/plane deltas are immediates
    const int kc0 = lane >> 4;
    const int arow0 = m0w + (lane & 15);
    const int brow0 = n0w + (lane & 15);
    uint32_t a0 = sb + (uint32_t)arow0 * 64
                + (uint32_t)((kc0 ^ ((arow0 >> 1) & 3)) << 4);
    uint32_t b0 = sb + 16384 + (uint32_t)brow0 * 64
                + (uint32_t)((kc0 ^ ((brow0 >> 1) & 3)) << 4);
    const uint32_t alim = a0 + 3 * STG;

    constexpr int nch = K >> 5;
    ISSUE(); ISSUE();

#pragma unroll 1
    for (int ch = 0; ch < nch; ch++) {
        asm volatile("cp.async.wait_group 1;" ::: "memory");
        __syncthreads();

#pragma unroll
        for (int kstep = 0; kstep < 2; kstep++) {
            const uint32_t ax = a0 ^ ((uint32_t)kstep << 5);
            const uint32_t bx = b0 ^ ((uint32_t)kstep << 5);
            uint32_t aH[4][4], aL[4][4], bh[2][4], bl[2][4];
            // ---- front burst: all 12 LDSMs (max MLP; first MMAs only need
            //      aH[0]/bh[0], so the tail streams under the MMA block) ----
#pragma unroll
            for (int mf = 0; mf < 4; mf++)
                ldsm_x4(aH[mf], ax + mf * 1024);
#pragma unroll
            for (int q = 0; q < 2; q++)
                ldsm_x4(bh[q], bx + q * 1024);
#pragma unroll
            for (int q = 0; q < 2; q++)
                ldsm_x4(bl[q], bx + 4096 + q * 1024);
#pragma unroll
            for (int mf = 0; mf < 4; mf++)
                ldsm_x4(aL[mf], ax + 8192 + mf * 1024);
            // pass hh
#pragma unroll
            for (int mf = 0; mf < 4; mf++)
#pragma unroll
                for (int q = 0; q < 2; q++) {
                    mma16816(acc[mf][q * 2 + 0], aH[mf], bh[q][0], bh[q][2]);
                    mma16816(acc[mf][q * 2 + 1], aH[mf], bh[q][1], bh[q][3]);
                }
            // deferred cp.async burst: LSU free while MMAs drain
            if (kstep == 0 && ch + 2 < nch) ISSUE();
            // pass hl
#pragma unroll
            for (int mf = 0; mf < 4; mf++)
#pragma unroll
                for (int q = 0; q < 2; q++) {
                    mma16816(acc[mf][q * 2 + 0], aH[mf], bl[q][0], bl[q][2]);
                    mma16816(acc[mf][q * 2 + 1], aH[mf], bl[q][1], bl[q][3]);
                }
            // pass lh
#pragma unroll
            for (int mf = 0; mf < 4; mf++)
#pragma unroll
                for (int q = 0; q < 2; q++) {
                    mma16816(acc[mf][q * 2 + 0], aL[mf], bh[q][0], bh[q][2]);
                    mma16816(acc[mf][q * 2 + 1], aL[mf], bh[q][1], bh[q][3]);
                }
        }
        a0 += STG; b0 += STG;
        if (a0 == alim) { a0 -= 3 * STG; b0 -= 3 * STG; }
    }
#undef ISSUE

    // ---- epilogue ----
    const int gr = lane >> 2;
    const int gc = (lane & 3) * 2;

    if (MODE == 0) {
#pragma unroll
        for (int mf = 0; mf < 4; mf++)
#pragma unroll
            for (int nf = 0; nf < 4; nf++) {
                const int row = m0 + m0w + mf * 16 + gr;
                const int col = n0 + n0w + nf * 8 + gc;
                float b0f = 0.f, b1f = 0.f;
                if (bias) { b0f = bias[col]; b1f = bias[col + 1]; }
                float2 v0 = make_float2(acc[mf][nf][0] + b0f, acc[mf][nf][1] + b1f);
                float2 v1 = make_float2(acc[mf][nf][2] + b0f, acc[mf][nf][3] + b1f);
                *reinterpret_cast<float2*>(Cf + (long long)row * N + col) = v0;
                *reinterpret_cast<float2*>(Cf + (long long)(row + 8) * N + col) = v1;
            }
    } else if (MODE == 3) {
        const int seg = n0 / segN;              // CTA-uniform (64 | segN)
        const int cwbase = n0 - seg * segN + n0w;
        if (seg < 2) {
            __nv_bfloat16* Dh = seg ? P1h : P0h;
            __nv_bfloat16* Dl = seg ? P1l : P0l;
#pragma unroll
            for (int mf = 0; mf < 4; mf++)
#pragma unroll
                for (int nf = 0; nf < 4; nf++) {
                    const int row = m0 + m0w + mf * 16 + gr;
                    const int col = cwbase + nf * 8 + gc;
                    const float b0f = bias[n0 + n0w + nf * 8 + gc];
                    const float b1f = bias[n0 + n0w + nf * 8 + gc + 1];
#pragma unroll
                    for (int half = 0; half < 2; half++) {
                        __nv_bfloat162 hh, ll;
                        split2(acc[mf][nf][half * 2 + 0] + b0f,
                               acc[mf][nf][half * 2 + 1] + b1f, hh, ll);
                        const long long idx = (long long)(row + half * 8) * segN + col;
                        *reinterpret_cast<__nv_bfloat162*>(Dh + idx) = hh;
                        *reinterpret_cast<__nv_bfloat162*>(Dl + idx) = ll;
                    }
                }
        } else {
            // V: transposed VT layout, staged via smem (reuses pipeline smem)
            __syncthreads();
            float* tw = reinterpret_cast<float*>(smem) + wid * 2080;  // 32x65
#pragma unroll
            for (int mf = 0; mf < 4; mf++)
#pragma unroll
                for (int nf = 0; nf < 4; nf++) {
                    const int rl = mf * 16 + gr;
                    const int cl = nf * 8 + gc;
                    tw[cl * 65 + rl]           = acc[mf][nf][0];
                    tw[(cl + 1) * 65 + rl]     = acc[mf][nf][1];
                    tw[cl * 65 + rl + 8]       = acc[mf][nf][2];
                    tw[(cl + 1) * 65 + rl + 8] = acc[mf][nf][3];
                }
            __syncwarp();
            const int g0 = m0 + m0w;
            const long long basev =
                (long long)(g0 >> 11) * segN * 2048 + (g0 & 2047);
#pragma unroll 4
            for (int c = 0; c < 32; c++) {
                const int colg = cwbase + c;
                const float bb = bias[n0 + n0w + c];
                const float v0 = tw[c * 65 + lane * 2] + bb;
                const float v1 = tw[c * 65 + lane * 2 + 1] + bb;
                __nv_bfloat162 hh, ll;
                split2(v0, v1, hh, ll);
                const long long idx = basev + (long long)colg * 2048 + lane * 2;
                *reinterpret_cast<__nv_bfloat162*>(P2h + idx) = hh;
                *reinterpret_cast<__nv_bfloat162*>(P2l + idx) = ll;
            }
        }
    } else {
        // MODE 4: PV1 + build_temp fused -> T planes (N=512)
        const float w1v = rw1[0], w2v = rw2[0];
#pragma unroll
        for (int mf = 0; mf < 4; mf++)
#pragma unroll
            for (int nf = 0; nf < 4; nf++) {
                const int col = n0 + n0w + nf * 8 + gc;
#pragma unroll
                for (int half = 0; half < 2; half++) {
                    const int row = m0 + m0w + mf * 16 + gr + half * 8;
                    const int grow = z * 2048 + row;
                    long long tok; int tcol; float2 res;
                    if (grow < 8192) {
                        tok = grow; tcol = col;
                        float2 yy = *reinterpret_cast<const float2*>(
                            ry + tok * 512 + col);
                        res.x = yy.x * w2v; res.y = yy.y * w2v;
                    } else {
                        tok = grow - 8192; tcol = col + 512;
                        float2 xx = *reinterpret_cast<const float2*>(
                            rx + tok * 512 + col);
                        res.x = xx.x * w1v; res.y = xx.y * w1v;
                    }
                    __nv_bfloat162 hh, ll;
                    split2(acc[mf][nf][half * 2 + 0] + res.x,
                           acc[mf][nf][half * 2 + 1] + res.y, hh, ll);
                    const long long idx = tok * 1024 + tcol;
                    *reinterpret_cast<__nv_bfloat162*>(P0h + idx) = hh;
                    *reinterpret_cast<__nv_bfloat162*>(P0l + idx) = ll;
                }
            }
    }
}

// ---------------------------------------------------------------------------
// split x and y fp32 -> stacked bf16 hi/lo planes (float4 granularity)
// ---------------------------------------------------------------------------
__global__ void __launch_bounds__(256)
split_xy(const float* __restrict__ x, const float* __restrict__ y,
         __nv_bfloat16* __restrict__ h, __nv_bfloat16* __restrict__ l,
         long long n4half)
{
    long long i = (long long)blockIdx.x * 256 + threadIdx.x;
    if (i >= 2 * n4half) return;
    const float* s = (i < n4half) ? x : y;
    const long long off = (i < n4half) ? i : i - n4half;
    float4 v = reinterpret_cast<const float4*>(s)[off];
    __nv_bfloat162 h0, l0, h1, l1;
    split2(v.x, v.y, h0, l0);
    split2(v.z, v.w, h1, l1);
    uint2 hh, ll;
    hh.x = *reinterpret_cast<uint32_t*>(&h0); hh.y = *reinterpret_cast<uint32_t*>(&h1);
    ll.x = *reinterpret_cast<uint32_t*>(&l0); ll.y = *reinterpret_cast<uint32_t*>(&l1);
    reinterpret_cast<uint2*>(h)[i] = hh;
    reinterpret_cast<uint2*>(l)[i] = ll;
}

// ---------------------------------------------------------------------------
// split 3 weight matrices into concatenated plane pair + concat biases
// ---------------------------------------------------------------------------
__global__ void __launch_bounds__(256)
split_w3(const float* __restrict__ s0, const float* __restrict__ s1,
         const float* __restrict__ s2,
         const float* __restrict__ b0, const float* __restrict__ b1,
         const float* __restrict__ b2,
         __nv_bfloat16* __restrict__ h, __nv_bfloat16* __restrict__ l,
         float* __restrict__ bcat, int rows, int K)
{
    const long long seglen = (long long)rows * K / 4;   // float4 per segment
    long long i = (long long)blockIdx.x * 256 + threadIdx.x;
    if (i < 3 * seglen) {
        const int seg = (int)(i / seglen);
        const long long off = i - (long long)seg * seglen;
        const float* s = (seg == 0) ? s0 : (seg == 1) ? s1 : s2;
        float4 v = reinterpret_cast<const float4*>(s)[off];
        __nv_bfloat162 h0, l0, h1, l1;
        split2(v.x, v.y, h0, l0);
        split2(v.z, v.w, h1, l1);
        uint2 hh, ll;
        hh.x = *reinterpret_cast<uint32_t*>(&h0); hh.y = *reinterpret_cast<uint32_t*>(&h1);
        ll.x = *reinterpret_cast<uint32_t*>(&l0); ll.y = *reinterpret_cast<uint32_t*>(&l1);
        reinterpret_cast<uint2*>(h)[i] = hh;
        reinterpret_cast<uint2*>(l)[i] = ll;
    }
    const long long t = (long long)blockIdx.x * 256 + threadIdx.x;
    if (t < 3 * rows) {
        const int seg = (int)(t / rows);
        const int off = (int)(t - seg * rows);
        bcat[t] = (seg == 0) ? b0[off] : (seg == 1) ? b1[off] : b2[off];
    }
}

// ---------------------------------------------------------------------------
// Row softmax over 2048 cols; fp32 in, split bf16 hi/lo out. Block = row.
// ---------------------------------------------------------------------------
__global__ void __launch_bounds__(256)
softmax2048(const float* __restrict__ S, __nv_bfloat16* __restrict__ Ph,
            __nv_bfloat16* __restrict__ Pl)
{
    const float* p = S + (long long)blockIdx.x * 2048;
    const int t = threadIdx.x;

    float v[8];
    {
        const float4* p4 = reinterpret_cast<const float4*>(p + t * 8);
        float4 a = p4[0], b = p4[1];
        v[0] = a.x; v[1] = a.y; v[2] = a.z; v[3] = a.w;
        v[4] = b.x; v[5] = b.y; v[6] = b.z; v[7] = b.w;
    }

    float m = v[0];
#pragma unroll
    for (int i = 1; i < 8; i++) m = fmaxf(m, v[i]);

    __shared__ float red[8];
#pragma unroll
    for (int o = 16; o > 0; o >>= 1) m = fmaxf(m, __shfl_xor_sync(0xffffffffu, m, o));
    if ((t & 31) == 0) red[t >> 5] = m;
    __syncthreads();
    if (t < 32) {
        float mm = (t < 8) ? red[t] : -3.4e38f;
#pragma unroll
        for (int o = 4; o > 0; o >>= 1) mm = fmaxf(mm, __shfl_xor_sync(0xffffffffu, mm, o));
        if (t == 0) red[0] = mm;
    }
    __syncthreads();
    m = red[0];
    __syncthreads();

    float s = 0.f;
#pragma unroll
    for (int i = 0; i < 8; i++) { v[i] = __expf(v[i] - m); s += v[i]; }
#pragma unroll
    for (int o = 16; o > 0; o >>= 1) s += __shfl_xor_sync(0xffffffffu, s, o);
    if ((t & 31) == 0) red[t >> 5] = s;
    __syncthreads();
    if (t < 32) {
        float ss = (t < 8) ? red[t] : 0.f;
#pragma unroll
        for (int o = 4; o > 0; o >>= 1) ss += __shfl_xor_sync(0xffffffffu, ss, o);
        if (t == 0) red[0] = ss;
    }
    __syncthreads();
    const float inv = 1.f / red[0];

    __nv_bfloat162* oh =
        reinterpret_cast<__nv_bfloat162*>(Ph + (long long)blockIdx.x * 2048 + t * 8);
    __nv_bfloat162* ol =
        reinterpret_cast<__nv_bfloat162*>(Pl + (long long)blockIdx.x * 2048 + t * 8);
#pragma unroll
    for (int i = 0; i < 4; i++) {
        __nv_bfloat162 hh, ll;
        split2(v[i * 2] * inv, v[i * 2 + 1] * inv, hh, ll);
        oh[i] = hh;
        ol[i] = ll;
    }
}

// ---------------------------------------------------------------------------
extern "C" void kernel_launch(void* const* d_in, const int* in_sizes, int n_in,
                              void* d_out, int out_size)
{
    (void)in_sizes; (void)n_in; (void)out_size;

    const float* x   = (const float*)d_in[0];
    const float* y   = (const float*)d_in[1];
    const float* Wq1 = (const float*)d_in[2];
    const float* bq1 = (const float*)d_in[3];
    const float* Wk1 = (const float*)d_in[4];
    const float* bk1 = (const float*)d_in[5];
    const float* Wv1 = (const float*)d_in[6];
    const float* bv1 = (const float*)d_in[7];
    const float* Wq2 = (const float*)d_in[8];
    const float* bq2 = (const float*)d_in[9];
    const float* Wk2 = (const float*)d_in[10];
    const float* bk2 = (const float*)d_in[11];
    const float* Wv2 = (const float*)d_in[12];
    const float* bv2 = (const float*)d_in[13];
    const float* w1  = (const float*)d_in[14];
    const float* w2  = (const float*)d_in[15];
    float* out = (float*)d_out;

    __nv_bfloat16 *xyh, *xyl, *w1h, *w1l, *w2h, *w2l;
    __nv_bfloat16 *Q1h, *Q1l, *K1h, *K1l, *VT1h, *VT1l, *Ph, *Pl;
    __nv_bfloat16 *Th, *Tl, *Q2h, *Q2l, *K2h, *K2l, *VT2h, *VT2l;
    float *S, *b1c, *b2c;
    cudaGetSymbolAddress((void**)&xyh, g_xyh);   cudaGetSymbolAddress((void**)&xyl, g_xyl);
    cudaGetSymbolAddress((void**)&w1h, g_w1h);   cudaGetSymbolAddress((void**)&w1l, g_w1l);
    cudaGetSymbolAddress((void**)&w2h, g_w2h);   cudaGetSymbolAddress((void**)&w2l, g_w2l);
    cudaGetSymbolAddress((void**)&b1c, g_b1);    cudaGetSymbolAddress((void**)&b2c, g_b2);
    cudaGetSymbolAddress((void**)&Q1h, g_Q1h);   cudaGetSymbolAddress((void**)&Q1l, g_Q1l);
    cudaGetSymbolAddress((void**)&K1h, g_K1h);   cudaGetSymbolAddress((void**)&K1l, g_K1l);
    cudaGetSymbolAddress((void**)&VT1h, g_VT1h); cudaGetSymbolAddress((void**)&VT1l, g_VT1l);
    cudaGetSymbolAddress((void**)&S, g_S);
    cudaGetSymbolAddress((void**)&Ph, g_Ph);     cudaGetSymbolAddress((void**)&Pl, g_Pl);
    cudaGetSymbolAddress((void**)&Th, g_Th);     cudaGetSymbolAddress((void**)&Tl, g_Tl);
    cudaGetSymbolAddress((void**)&Q2h, g_Q2h);   cudaGetSymbolAddress((void**)&Q2l, g_Q2l);
    cudaGetSymbolAddress((void**)&K2h, g_K2h);   cudaGetSymbolAddress((void**)&K2l, g_K2l);
    cudaGetSymbolAddress((void**)&VT2h, g_VT2h); cudaGetSymbolAddress((void**)&VT2l, g_VT2l);

    cudaFuncSetAttribute(gemm_bf3<512, 3>,  cudaFuncAttributeMaxDynamicSharedMemorySize, SMEM_BYTES);
    cudaFuncSetAttribute(gemm_bf3<512, 0>,  cudaFuncAttributeMaxDynamicSharedMemorySize, SMEM_BYTES);
    cudaFuncSetAttribute(gemm_bf3<2048, 4>, cudaFuncAttributeMaxDynamicSharedMemorySize, SMEM_BYTES);
    cudaFuncSetAttribute(gemm_bf3<1024, 3>, cudaFuncAttributeMaxDynamicSharedMemorySize, SMEM_BYTES);
    cudaFuncSetAttribute(gemm_bf3<1024, 0>, cudaFuncAttributeMaxDynamicSharedMemorySize, SMEM_BYTES);
    cudaFuncSetAttribute(gemm_bf3<2048, 0>, cudaFuncAttributeMaxDynamicSharedMemorySize, SMEM_BYTES);

    const dim3 blk(256);
    const dim3 gblk(128);
    const long long HX = 8192LL * 512;
    const float* NF = nullptr;

    // 1: split x,y
    split_xy<<<(int)((HX / 2 + 255) / 256), blk>>>(x, y, xyh, xyl, HX / 4);
    // 2,3: split+concat weights/biases
    split_w3<<<(3 * 512 * 512 / 4 + 255) / 256, blk>>>(Wq1, Wk1, Wv1, bq1, bk1, bv1,
                                                       w1h, w1l, b1c, 512, 512);
    split_w3<<<(3 * 1024 * 1024 / 4 + 255) / 256, blk>>>(Wq2, Wk2, Wv2, bq2, bk2, bv2,
                                                         w2h, w2l, b2c, 1024, 1024);

    // 4: QKV1 fused (M=16384, N=1536, K=512), routing epilogue
    dim3 g1(1536 / 64, 16384 / 128);
    gemm_bf3<512, 3><<<g1, gblk, SMEM_BYTES>>>(xyh, xyl, w1h, w1l, b1c,
                                       nullptr, Q1h, Q1l, K1h, K1l, VT1h, VT1l,
                                       NF, NF, NF, NF,
                                       16384, 1536, 0, 0, 0, 512);

    // 5: scores1 (z=8)
    dim3 gs1(2048 / 64, 2048 / 128, 8);
    gemm_bf3<512, 0><<<gs1, gblk, SMEM_BYTES>>>(Q1h, Q1l, K1h, K1l, nullptr,
                                        S, nullptr, nullptr, nullptr, nullptr,
                                        nullptr, nullptr, NF, NF, NF, NF,
                                        2048, 2048,
                                        2048LL * 512, 2048LL * 512, 2048LL * 2048, 0);
    // 6: softmax1
    softmax2048<<<16384, blk>>>(S, Ph, Pl);
    // 7: PV1 + build_temp fused -> T planes
    dim3 gp1(512 / 64, 2048 / 128, 8);
    gemm_bf3<2048, 4><<<gp1, gblk, SMEM_BYTES>>>(Ph, Pl, VT1h, VT1l, nullptr,
                                        nullptr, Th, Tl, nullptr, nullptr,
                                        nullptr, nullptr, x, y, w1, w2,
                                        2048, 512,
                                        2048LL * 2048, 512LL * 2048, 0, 0);

    // 8: QKV2 fused (M=8192, N=3072, K=1024)
    dim3 g2(3072 / 64, 8192 / 128);
    gemm_bf3<1024, 3><<<g2, gblk, SMEM_BYTES>>>(Th, Tl, w2h, w2l, b2c,
                                       nullptr, Q2h, Q2l, K2h, K2l, VT2h, VT2l,
                                       NF, NF, NF, NF,
                                       8192, 3072, 0, 0, 0, 1024);

    // 9: scores2 (z=4)
    dim3 gs2(2048 / 64, 2048 / 128, 4);
    gemm_bf3<1024, 0><<<gs2, gblk, SMEM_BYTES>>>(Q2h, Q2l, K2h, K2l, nullptr,
                                        S, nullptr, nullptr, nullptr, nullptr,
                                        nullptr, nullptr, NF, NF, NF, NF,
                                        2048, 2048,
                                        2048LL * 1024, 2048LL * 1024, 2048LL * 2048, 0);
    // 10: softmax2
    softmax2048<<<8192, blk>>>(S, Ph, Pl);
    // 11: PV2 -> out (fp32)
    dim3 gp2(1024 / 64, 2048 / 128, 4);
    gemm_bf3<2048, 0><<<gp2, gblk, SMEM_BYTES>>>(Ph, Pl, VT2h, VT2l, nullptr,
                                        out, nullptr, nullptr, nullptr, nullptr,
                                        nullptr, nullptr, NF, NF, NF, NF,
                                        2048, 1024,
                                        2048LL * 2048, 1024LL * 2048, 2048LL * 1024, 0);
}